// round 1
// baseline (speedup 1.0000x reference)
#include <cuda_runtime.h>
#include <cuda_bf16.h>
#include <cstdint>
#include <math.h>

// Problem constants
constexpr int M_ROWS = 65536;   // B*S*G = 16*2048*2
constexpr int N_V    = 320;     // codebook size
constexpr int K_D    = 384;     // codebook dim
constexpr int OUT_D  = 768;
constexpr int GV     = 640;     // G*V
constexpr float EPS_G  = 1e-10f;
constexpr float MARGIN = 0.375f;

// Scratch (device globals; no allocation allowed)
__device__ __nv_bfloat16 g_Wt_bf16[N_V * K_D];  // W_logits transposed, bf16 [320][384]
__device__ float         g_Wt_f32 [N_V * K_D];  // W_logits transposed, fp32 [320][384]
__device__ float         g_E[GV * OUT_D];       // E[g*320+v][o] = codebook row @ W_out half
__device__ int           g_idx[M_ROWS];

__device__ __forceinline__ float gumbelf(float u) {
    return -logf(-logf(u + EPS_G) + EPS_G);
}

__device__ __forceinline__ void ldsm_x4(uint32_t* r, uint32_t addr) {
    asm volatile("ldmatrix.sync.aligned.m8n8.x4.shared.b16 {%0,%1,%2,%3}, [%4];\n"
        : "=r"(r[0]), "=r"(r[1]), "=r"(r[2]), "=r"(r[3]) : "r"(addr));
}

__device__ __forceinline__ void mma_bf16(float* c, const uint32_t* a, const uint32_t* b) {
    asm volatile("mma.sync.aligned.m16n8k16.row.col.f32.bf16.bf16.f32 "
        "{%0,%1,%2,%3}, {%4,%5,%6,%7}, {%8,%9}, {%0,%1,%2,%3};\n"
        : "+f"(c[0]), "+f"(c[1]), "+f"(c[2]), "+f"(c[3])
        : "r"(a[0]), "r"(a[1]), "r"(a[2]), "r"(a[3]), "r"(b[0]), "r"(b[1]));
}

// ---------------------------------------------------------------------------
// Kernel 0: transpose W_logits [384][320] -> Wt [320][384] in bf16 and fp32
// ---------------------------------------------------------------------------
__global__ void prep_wt_kernel(const float* __restrict__ W) {
    int i = blockIdx.x * blockDim.x + threadIdx.x;
    if (i < K_D * N_V) {
        int k = i / N_V, n = i % N_V;
        float v = W[i];
        g_Wt_f32 [n * K_D + k] = v;
        g_Wt_bf16[n * K_D + k] = __float2bfloat16(v);
    }
}

// ---------------------------------------------------------------------------
// Kernel 1: E[gv][o] = sum_d codebooks[gv][d] * W_out[g*384+d][o]  (fp32 GEMM)
// grid (768/64, 640/32), 256 threads, thread tile 2x4
// ---------------------------------------------------------------------------
__global__ __launch_bounds__(256) void compute_E_kernel(
    const float* __restrict__ CB, const float* __restrict__ Wout)
{
    __shared__ float As2[32][17];
    __shared__ float Bs2[16][68];
    const int t  = threadIdx.x;
    const int ty = t >> 4, tx = t & 15;
    const int gv0 = blockIdx.y * 32;
    const int o0  = blockIdx.x * 64;
    const int goff = (gv0 >= 320) ? 384 : 0;   // 320 % 32 == 0 -> uniform per block
    float acc0[4] = {0.f,0.f,0.f,0.f}, acc1[4] = {0.f,0.f,0.f,0.f};

    for (int k0 = 0; k0 < K_D; k0 += 16) {
        #pragma unroll
        for (int i = 0; i < 2; ++i) {
            int idx = t + i * 256;
            int r = idx >> 4, c = idx & 15;
            As2[r][c] = CB[(size_t)(gv0 + r) * K_D + k0 + c];
        }
        #pragma unroll
        for (int i = 0; i < 4; ++i) {
            int idx = t + i * 256;
            int r = idx >> 6, c = idx & 63;
            Bs2[r][c] = Wout[(size_t)(goff + k0 + r) * OUT_D + o0 + c];
        }
        __syncthreads();
        #pragma unroll
        for (int k = 0; k < 16; ++k) {
            float a0 = As2[ty][k], a1 = As2[ty + 16][k];
            #pragma unroll
            for (int j = 0; j < 4; ++j) {
                float b = Bs2[k][tx * 4 + j];
                acc0[j] = fmaf(a0, b, acc0[j]);
                acc1[j] = fmaf(a1, b, acc1[j]);
            }
        }
        __syncthreads();
    }
    #pragma unroll
    for (int j = 0; j < 4; ++j) {
        g_E[(size_t)(gv0 + ty)      * OUT_D + o0 + tx * 4 + j] = acc0[j];
        g_E[(size_t)(gv0 + ty + 16) * OUT_D + o0 + tx * 4 + j] = acc1[j];
    }
}

// ---------------------------------------------------------------------------
// Kernel 2: fused bf16-HMMA logits GEMM + gumbel + argmax + fp64 rescue
//   C[65536,320] = z(as [65536,384]) @ W[384,320]; idx = row argmax of C+gumbel
// grid 1024 (BM=64), 512 threads (16 warps, warp grid 4m x 4n)
// ---------------------------------------------------------------------------
__global__ __launch_bounds__(512, 1) void logits_argmax_kernel(
    const float* __restrict__ z, const float* __restrict__ noise,
    const float* __restrict__ blog)
{
    // Union: tiles (As 5120B + Ws 25600B) alias logits buffer (40960B)
    __shared__ __align__(16) unsigned char smem_raw[64 * N_V * 2];
    __nv_bfloat16* As = reinterpret_cast<__nv_bfloat16*>(smem_raw);          // [64][40]
    __nv_bfloat16* Ws = reinterpret_cast<__nv_bfloat16*>(smem_raw + 5120);   // [320][40]
    __nv_bfloat16* Lg = reinterpret_cast<__nv_bfloat16*>(smem_raw);          // [64][320]

    const int tid  = threadIdx.x;
    const int lane = tid & 31, wid = tid >> 5;
    const int warp_m = wid & 3, warp_n = wid >> 2;
    const int row0 = blockIdx.x * 64;

    float acc[10][4];
    #pragma unroll
    for (int i = 0; i < 10; ++i)
        #pragma unroll
        for (int j = 0; j < 4; ++j) acc[i][j] = 0.f;

    const int ar = tid >> 3;          // A-tile row this thread loads (0..63)
    const int ac = (tid & 7) * 4;     // A-tile col (float4)

    for (int kt = 0; kt < 12; ++kt) {
        const int k0 = kt * 32;
        // A tile: fp32 global -> bf16 smem (z converted on the fly, read once)
        {
            float4 v = *reinterpret_cast<const float4*>(
                &z[(size_t)(row0 + ar) * K_D + k0 + ac]);
            __nv_bfloat162 p0 = __floats2bfloat162_rn(v.x, v.y);
            __nv_bfloat162 p1 = __floats2bfloat162_rn(v.z, v.w);
            *reinterpret_cast<__nv_bfloat162*>(&As[ar * 40 + ac])     = p0;
            *reinterpret_cast<__nv_bfloat162*>(&As[ar * 40 + ac + 2]) = p1;
        }
        // W tile: 320 x 32 bf16
        #pragma unroll
        for (int i = 0; i < 5; ++i) {
            int idx = tid + i * 512;
            int r = idx >> 3, c = (idx & 7) * 4;
            uint2 w = *reinterpret_cast<const uint2*>(&g_Wt_bf16[r * K_D + k0 + c]);
            *reinterpret_cast<uint2*>(&Ws[r * 40 + c]) = w;
        }
        __syncthreads();
        #pragma unroll
        for (int ks = 0; ks < 2; ++ks) {
            const int kk = ks * 16;
            uint32_t a[4];
            {
                int i = lane & 7, j = lane >> 3;
                int r = warp_m * 16 + (j & 1) * 8 + i;
                int c = kk + (j >> 1) * 8;
                ldsm_x4(a, (uint32_t)__cvta_generic_to_shared(&As[r * 40 + c]));
            }
            #pragma unroll
            for (int p = 0; p < 5; ++p) {
                uint32_t b[4];
                int i = lane & 7, j = lane >> 3;
                int r = warp_n * 80 + p * 16 + (j >> 1) * 8 + i;
                int c = kk + (j & 1) * 8;
                ldsm_x4(b, (uint32_t)__cvta_generic_to_shared(&Ws[r * 40 + c]));
                mma_bf16(acc[2 * p],     a, b);
                mma_bf16(acc[2 * p + 1], a, b + 2);
            }
        }
        __syncthreads();
    }

    // Phase 2: add bias + gumbel, stash approx logits (bf16) in smem
    const int gid = lane >> 2, tig = lane & 3;
    const int r1 = warp_m * 16 + gid;
    const int r2 = r1 + 8;
    #pragma unroll
    for (int t = 0; t < 10; ++t) {
        int n = warp_n * 80 + t * 8 + tig * 2;
        float2 u1 = *reinterpret_cast<const float2*>(&noise[(size_t)(row0 + r1) * N_V + n]);
        float2 u2 = *reinterpret_cast<const float2*>(&noise[(size_t)(row0 + r2) * N_V + n]);
        float b0 = blog[n], b1 = blog[n + 1];
        Lg[r1 * N_V + n]     = __float2bfloat16(acc[t][0] + b0 + gumbelf(u1.x));
        Lg[r1 * N_V + n + 1] = __float2bfloat16(acc[t][1] + b1 + gumbelf(u1.y));
        Lg[r2 * N_V + n]     = __float2bfloat16(acc[t][2] + b0 + gumbelf(u2.x));
        Lg[r2 * N_V + n + 1] = __float2bfloat16(acc[t][3] + b1 + gumbelf(u2.y));
    }
    __syncthreads();

    // Phase 3: per-row argmax; rescue ambiguous rows with exact fp64 rescoring
    #pragma unroll 1
    for (int rr = 0; rr < 4; ++rr) {
        const int r = wid * 4 + rr;              // 16 warps x 4 rows = 64
        const __nv_bfloat16* Lrow = &Lg[r * N_V];
        float v[10];
        float best = -1e30f; int bestc = 0;
        #pragma unroll
        for (int c = 0; c < 10; ++c) {
            v[c] = __bfloat162float(Lrow[lane * 10 + c]);
            if (v[c] > best) { best = v[c]; bestc = lane * 10 + c; }
        }
        #pragma unroll
        for (int off = 16; off; off >>= 1) {
            float ov = __shfl_xor_sync(0xffffffffu, best, off);
            int   oc = __shfl_xor_sync(0xffffffffu, bestc, off);
            if (ov > best || (ov == best && oc < bestc)) { best = ov; bestc = oc; }
        }
        const float thresh = best - MARGIN;
        int cnt = 0;
        #pragma unroll
        for (int c = 0; c < 10; ++c) cnt += (v[c] >= thresh) ? 1 : 0;
        #pragma unroll
        for (int off = 16; off; off >>= 1) cnt += __shfl_xor_sync(0xffffffffu, cnt, off);

        const int gRow = row0 + r;
        if (cnt <= 1) {
            if (lane == 0) g_idx[gRow] = bestc;
        } else {
            // fp64 rescore of every candidate (warp-parallel dot over k)
            double bb = -1e300; int bbc = 0x7fffffff;
            const float* zrow = &z[(size_t)gRow * K_D];
            #pragma unroll 1
            for (int c = 0; c < 10; ++c) {
                unsigned ball = __ballot_sync(0xffffffffu, v[c] >= thresh);
                while (ball) {
                    int src = __ffs(ball) - 1; ball &= ball - 1;
                    int col = src * 10 + c;
                    const float* wrow = &g_Wt_f32[col * K_D];
                    double s = 0.0;
                    #pragma unroll
                    for (int k = 0; k < 12; ++k) {
                        int kk2 = k * 32 + lane;
                        s += (double)zrow[kk2] * (double)wrow[kk2];
                    }
                    #pragma unroll
                    for (int off = 16; off; off >>= 1)
                        s += __shfl_xor_sync(0xffffffffu, s, off);
                    float u = noise[(size_t)gRow * N_V + col];
                    double lgt = s + (double)blog[col] + (double)gumbelf(u);
                    if (lgt > bb || (lgt == bb && col < bbc)) { bb = lgt; bbc = col; }
                }
            }
            if (lane == 0) g_idx[gRow] = bbc;
        }
    }
}

// ---------------------------------------------------------------------------
// Kernel 3: out[t] = E[idx0] + E[320+idx1] + b_out   (grid 32768, 192 threads)
// ---------------------------------------------------------------------------
__global__ void gather_out_kernel(const float* __restrict__ b_out, float* __restrict__ out)
{
    const int tk = blockIdx.x;
    const int i0 = g_idx[2 * tk];
    const int i1 = g_idx[2 * tk + 1];
    const float4* e0 = reinterpret_cast<const float4*>(&g_E[(size_t)i0 * OUT_D]);
    const float4* e1 = reinterpret_cast<const float4*>(&g_E[(size_t)(320 + i1) * OUT_D]);
    const float4* b4 = reinterpret_cast<const float4*>(b_out);
    float4* o4 = reinterpret_cast<float4*>(out + (size_t)tk * OUT_D);
    const int j = threadIdx.x;   // 192 = 768/4
    float4 a = e0[j], b = e1[j], c = b4[j];
    o4[j] = make_float4(a.x + b.x + c.x, a.y + b.y + c.y,
                        a.z + b.z + c.z, a.w + b.w + c.w);
}

// ---------------------------------------------------------------------------
extern "C" void kernel_launch(void* const* d_in, const int* in_sizes, int n_in,
                              void* d_out, int out_size)
{
    // Select inputs by element count (robust to ordering): all sizes distinct.
    const float *z = nullptr, *noise = nullptr, *Wlog = nullptr, *blog = nullptr,
                *CB = nullptr, *Wout = nullptr, *bout = nullptr;
    for (int i = 0; i < n_in; ++i) {
        switch (in_sizes[i]) {
            case 25165824: z     = (const float*)d_in[i]; break; // 16*2048*768
            case 20971520: noise = (const float*)d_in[i]; break; // 16*2048*2*320
            case 122880:   Wlog  = (const float*)d_in[i]; break; // 384*320
            case 320:      blog  = (const float*)d_in[i]; break;
            case 245760:   CB    = (const float*)d_in[i]; break; // 2*320*384
            case 589824:   Wout  = (const float*)d_in[i]; break; // 768*768
            case 768:      bout  = (const float*)d_in[i]; break;
        }
    }
    float* out = (float*)d_out;

    prep_wt_kernel<<<(N_V * K_D + 255) / 256, 256>>>(Wlog);
    compute_E_kernel<<<dim3(OUT_D / 64, GV / 32), 256>>>(CB, Wout);
    logits_argmax_kernel<<<M_ROWS / 64, 512>>>(z, noise, blog);
    gather_out_kernel<<<M_ROWS / 2, 192>>>(bout, out);
}